// round 11
// baseline (speedup 1.0000x reference)
#include <cuda_runtime.h>
#include <cstdint>

#define B 16
#define G 128
#define P 8000
#define R 200
#define POS_CAP 66
#define NSPLIT 16
#define CHUNK 500          // 16 * 500 = 8000 exactly
#define NBINS 1024
#define CAND_CAP 512
#define NB (B * NSPLIT)    // 256 persistent blocks, 512 thr, 2/SM co-resident

// ---------------- scratch (no allocations allowed) ----------------
__device__ unsigned long long d_gbest[B * G];
__device__ int d_parg[B * P];
__device__ unsigned long long d_poskeys[B * P];
__device__ unsigned long long d_negkeys[B * P];
__device__ int d_poscount[B];
__device__ int d_negcount[B];
__device__ int d_posidx[B * POS_CAP];
__device__ int d_negidx[B * R];
__device__ int d_matched[B * G];
__device__ volatile unsigned d_bar;

// ---------------- threefry2x32 (exact JAX, partitionable path) ----------
__device__ __forceinline__ uint32_t rotl32(uint32_t v, int d) {
    return (v << d) | (v >> (32 - d));
}

__device__ __forceinline__ void threefry(uint32_t k0, uint32_t k1, uint32_t x0,
                                         uint32_t x1, uint32_t& o0, uint32_t& o1) {
    uint32_t ks2 = k0 ^ k1 ^ 0x1BD11BDAu;
    x0 += k0; x1 += k1;
#define TFR(r) { x0 += x1; x1 = rotl32(x1, r); x1 ^= x0; }
    TFR(13) TFR(15) TFR(26) TFR(6)
    x0 += k1; x1 += ks2 + 1u;
    TFR(17) TFR(29) TFR(16) TFR(24)
    x0 += ks2; x1 += k0 + 2u;
    TFR(13) TFR(15) TFR(26) TFR(6)
    x0 += k0; x1 += k1 + 3u;
    TFR(17) TFR(29) TFR(16) TFR(24)
    x0 += k1; x1 += ks2 + 4u;
    TFR(13) TFR(15) TFR(26) TFR(6)
    x0 += ks2; x1 += k0 + 5u;
#undef TFR
    o0 = x0; o1 = x1;
}

__device__ __forceinline__ void batch_keys(int b, uint32_t& k1a, uint32_t& k1b,
                                           uint32_t& k2a, uint32_t& k2b) {
    uint32_t kb0, kb1;
    threefry(0u, 42u, 0u, (uint32_t)b, kb0, kb1);   // split(key(42), 16)[b]
    threefry(kb0, kb1, 0u, 0u, k1a, k1b);           // split(key_b, 2)[0]
    threefry(kb0, kb1, 0u, 1u, k2a, k2b);           // split(key_b, 2)[1]
}

// u = m * 2^-23, m = (o0^o1)>>9: strictly monotonic in m -> sort on mantissa
__device__ __forceinline__ uint32_t umant(uint32_t ka, uint32_t kb, int p) {
    uint32_t a, c;
    threefry(ka, kb, 0u, (uint32_t)p, a, c);
    return (a ^ c) >> 9;
}

__device__ __forceinline__ uint32_t ford(float f) {
    uint32_t u = __float_as_uint(f);
    return (u & 0x80000000u) ? ~u : (u | 0x80000000u);
}

// ---------------- software grid barrier ----------------
__device__ __forceinline__ void gsync(unsigned target) {
    __syncthreads();
    if (threadIdx.x == 0) {
        __threadfence();
        atomicAdd((unsigned*)&d_bar, 1u);
        while (d_bar < target) __nanosleep(32);
        __threadfence();
    }
    __syncthreads();
}

// ---------------- init: re-zero accumulators each launch ----------------
__global__ void k_init() {
    int i = blockIdx.x * blockDim.x + threadIdx.x;
    if (i == 0) *(unsigned*)&d_bar = 0u;
    if (i < B * G) { d_gbest[i] = 0ull; d_matched[i] = 0; }
    if (i < B) { d_poscount[i] = 0; d_negcount[i] = 0; }
}

// ---------------- persistent main kernel ----------------
__global__ __launch_bounds__(512, 2)
void k_main(const float* __restrict__ gt, const int* __restrict__ gcls,
            const float* __restrict__ pr, float* __restrict__ out,
            float* __restrict__ miss_out) {
    __shared__ __align__(16) unsigned char s_raw[18432];
    __shared__ int s_wcnt[4], s_woff[4], s_ng;
    __shared__ uint32_t s_rem[16];            // CHUNK/32 words
    __shared__ int s_T, s_cnt, s_miss;

    int bid = blockIdx.x;
    int tid = threadIdx.x;
    int lane = tid & 31;
    int wid = tid >> 5;

    int b = bid / NSPLIT;
    int split = bid % NSPLIT;
    int pbase = split * CHUNK;

    // phase-1 smem layout
    float4* sg4 = (float4*)s_raw;                         // 2048B
    float* sga = (float*)(s_raw + 2048);                  // 512B
    int* sglist = (int*)(s_raw + 2560);                   // 512B
    float* ppy1 = (float*)(s_raw + 3072);                 // 2048B each
    float* ppx1 = (float*)(s_raw + 5120);
    float* ppy2 = (float*)(s_raw + 7168);
    float* ppx2 = (float*)(s_raw + 9216);
    float* pap  = (float*)(s_raw + 11264);                // <0 => invalid

    // ---------- load GTs (compact valid, order-preserving) + proposals ----------
    {
        bool gvalid = false;
        float a0 = 0, a1 = 0, a2 = 0, a3 = 0;
        if (tid < G) {
            const float* gp = gt + ((size_t)b * G + tid) * 5;
            a0 = gp[0]; a1 = gp[1]; a2 = gp[2]; a3 = gp[3];
            gvalid = (gp[4] != 0.0f);
        }
        if (tid < G) {
            unsigned ball = __ballot_sync(0xFFFFFFFFu, gvalid);
            if (lane == 0) s_wcnt[wid] = __popc(ball);
        }
        // proposals -> smem SoA
        if (tid < CHUNK) {
            const float* pp = pr + ((size_t)b * P + pbase + tid) * 5;
            float q0 = pp[0], q1 = pp[1], q2 = pp[2], q3 = pp[3];
            bool pvl = (pp[4] != 0.0f);
            ppy1[tid] = q0; ppx1[tid] = q1; ppy2[tid] = q2; ppx2[tid] = q3;
            pap[tid] = pvl ? __fmul_rn(__fsub_rn(q3, q1), __fsub_rn(q2, q0)) : -1.0f;
        } else {
            pap[tid] = -1.0f;
        }
        __syncthreads();
        if (tid == 0) {
            int off = 0;
            for (int w = 0; w < 4; ++w) { s_woff[w] = off; off += s_wcnt[w]; }
            s_ng = off;
        }
        __syncthreads();
        if (tid < G && gvalid) {
            unsigned ball = __ballot_sync(__activemask(), true);
            unsigned below = ball & ((1u << lane) - 1u);
            int rank = s_woff[wid] + __popc(below);
            sg4[rank] = make_float4(a0, a1, a2, a3);
            sga[rank] = __fmul_rn(__fsub_rn(a3, a1), __fsub_rn(a2, a0));
            sglist[rank] = tid;
        }
        __syncthreads();
    }
    int ng = s_ng;

    // ---------- pass A: per-proposal argmax over g (pure registers) ----------
    float best = -2.0f;
    int barg = 0;
    bool pv = false;
    {
        float p0 = 0, p1 = 0, p2 = 0, p3 = 0, ap = 0;
        if (tid < CHUNK) {
            p0 = ppy1[tid]; p1 = ppx1[tid]; p2 = ppy2[tid]; p3 = ppx2[tid];
            ap = pap[tid];
            pv = (ap >= 0.0f);
            // recompute ap for invalid-proposal case irrelevant (pv gates)
        }
        for (int i = 0; i < ng; ++i) {
            float4 gb = sg4[i];
            float iw = fmaxf(0.0f, __fsub_rn(fminf(gb.w, p3), fmaxf(gb.y, p1)));
            float ih = fmaxf(0.0f, __fsub_rn(fminf(gb.z, p2), fmaxf(gb.x, p0)));
            float inter = __fmul_rn(iw, ih);
            float denom = __fsub_rn(__fadd_rn(sga[i], ap), inter);
            float iou = __fdiv_rn(inter, denom);
            float v = (pv && tid < CHUNK) ? iou : -1.0f;
            if (v > best) { best = v; barg = i; }   // first-index argmax
        }
    }

    // ---------- pass B: per-g argmax over p (one warp per g) ----------
    for (int g = wid; g < ng; g += 16) {
        float4 gb = sg4[g];
        float ga = sga[g];
        uint32_t bfv = 0u;
        uint32_t bp = 0u;
        // lane covers strided p: idx = lane + 32*j (conflict-free SoA LDS);
        // in-lane strict > keeps lowest j (= lowest p within lane's set)
        #pragma unroll 4
        for (int j = 0; j < 16; ++j) {
            int idx = lane + 32 * j;
            float ap = pap[idx];
            if (ap >= 0.0f) {
                float q0 = ppy1[idx], q1 = ppx1[idx], q2 = ppy2[idx], q3 = ppx2[idx];
                float iw = fmaxf(0.0f, __fsub_rn(fminf(gb.w, q3), fmaxf(gb.y, q1)));
                float ih = fmaxf(0.0f, __fsub_rn(fminf(gb.z, q2), fmaxf(gb.x, q0)));
                float inter = __fmul_rn(iw, ih);
                float denom = __fsub_rn(__fadd_rn(ga, ap), inter);
                float iou = __fdiv_rn(inter, denom);
                uint32_t fv = ford(iou);
                if (fv > bfv) { bfv = fv; bp = (uint32_t)(pbase + idx); }
            }
        }
        uint32_t wmax = __reduce_max_sync(0xFFFFFFFFu, bfv);
        uint32_t pc = (bfv == wmax && wmax != 0u) ? bp : 0xFFFFFFFFu;
        uint32_t pmin = __reduce_min_sync(0xFFFFFFFFu, pc);  // global lowest p
        if (lane == 0 && wmax != 0u) {
            unsigned long long key = (((unsigned long long)wmax) << 32) |
                                     (unsigned long long)(0xFFFFFFFFu - pmin);
            atomicMax(&d_gbest[(size_t)b * G + sglist[g]], key);
        }
    }

    // ---------- phase-2 pre: speculative RNG key write (overlaps barrier) ----
    {
        uint32_t k1a, k1b, k2a, k2b;
        batch_keys(b, k1a, k1b, k2a, k2b);
        if (tid < CHUNK) {
            int p = pbase + tid;
            size_t bp2 = (size_t)b * P + p;
            unsigned long long pk = 0ull, nk = 0ull;
            if (pv) {
                uint32_t plow = 0xFFFFFFFFu - (uint32_t)p;
                if (best >= 0.5f) {
                    uint32_t m = umant(k1a, k1b, p);
                    pk = (((unsigned long long)m) << 32) | (unsigned long long)plow;
                } else {
                    uint32_t m = umant(k2a, k2b, p);
                    nk = (((unsigned long long)m) << 32) | (unsigned long long)plow;
                }
            }
            d_poskeys[bp2] = pk;
            d_negkeys[bp2] = nk;
        }
    }

    gsync(NB);

    // ---------- fixup: removed set, zeroing, counts, matched, parg ----------
    {
        if (tid < 16) s_rem[tid] = 0u;
        __syncthreads();
        if (tid < G) {
            if (gt[((size_t)b * G + tid) * 5 + 4] != 0.0f) {
                unsigned long long key = d_gbest[b * G + tid];
                int arg = (int)(0xFFFFFFFFu - (uint32_t)(key & 0xFFFFFFFFull));
                int rel = arg - pbase;
                if (rel >= 0 && rel < CHUNK)
                    atomicOr(&s_rem[rel >> 5], 1u << (rel & 31));
            }
        }
        __syncthreads();

        int nposl = 0, nnegl = 0;
        if (tid < CHUNK && pv) {
            int p = pbase + tid;
            size_t bp2 = (size_t)b * P + p;
            bool removed = ((s_rem[tid >> 5] >> (tid & 31)) & 1u) != 0;
            bool pos = (best >= 0.5f);
            if (removed) {
                if (pos) d_poskeys[bp2] = 0ull;
                else     d_negkeys[bp2] = 0ull;
            } else {
                if (pos) {
                    nposl = 1;
                    int gg = sglist[barg];
                    d_matched[b * G + gg] = 1;
                    d_parg[bp2] = gg;
                } else {
                    nnegl = 1;
                }
            }
        }
        nposl = __reduce_add_sync(0xFFFFFFFFu, nposl);
        nnegl = __reduce_add_sync(0xFFFFFFFFu, nnegl);
        if (lane == 0) {
            if (nposl) atomicAdd(&d_poscount[b], nposl);
            if (nnegl) atomicAdd(&d_negcount[b], nnegl);
        }
    }

    gsync(2 * NB);

    // ---------- select (pos + neg) + emit: 16 blocks, one per batch ----------
    if (bid >= B) return;
    int eb = bid;   // batch this block emits

    uint32_t* hist = (uint32_t*)s_raw;
    uint32_t* sfx = hist + NBINS;
    uint32_t* sfx2 = sfx + NBINS;
    unsigned long long* cand = (unsigned long long*)(sfx2 + NBINS);
    uint32_t* cand_p = (uint32_t*)(cand + CAND_CAP);

    for (int sel = 0; sel < 2; ++sel) {
        bool isPos = (sel == 0);
        int K = isPos ? POS_CAP : R;
        const unsigned long long* src =
            isPos ? (d_poskeys + (size_t)eb * P) : (d_negkeys + (size_t)eb * P);

        for (int i = tid; i < NBINS; i += 512) hist[i] = 0u;
        if (tid == 0) { s_T = 0; s_cnt = 0; }
        __syncthreads();

        for (int p = tid; p < P; p += 512) {
            unsigned long long key = src[p];
            if (key != 0ull) atomicAdd(&hist[(uint32_t)(key >> 45)], 1u);
        }
        __syncthreads();

        for (int i = tid; i < NBINS; i += 512) sfx[i] = hist[i];
        __syncthreads();
        uint32_t* cur = sfx;
        uint32_t* nxt = sfx2;
        for (int d = 1; d < NBINS; d <<= 1) {
            for (int i = tid; i < NBINS; i += 512) {
                uint32_t v = cur[i];
                if (i + d < NBINS) v += cur[i + d];
                nxt[i] = v;
            }
            __syncthreads();
            uint32_t* t = cur; cur = nxt; nxt = t;
        }

        for (int i = tid; i < NBINS; i += 512) {
            if (cur[i] >= (uint32_t)K && (i == NBINS - 1 || cur[i + 1] < (uint32_t)K))
                s_T = i;
        }
        __syncthreads();
        int T = s_T;

        for (int p = tid; p < P; p += 512) {
            unsigned long long key = src[p];
            if (key != 0ull && (int)(key >> 45) >= T) {
                int pos = atomicAdd(&s_cnt, 1);
                if (pos < CAND_CAP) { cand[pos] = key; cand_p[pos] = (uint32_t)p; }
            }
        }
        __syncthreads();
        int cnt = min(s_cnt, CAND_CAP);

        for (int i = tid; i < cnt; i += 512) {
            unsigned long long ki = cand[i];
            int rank = 0;
            for (int j = 0; j < cnt; ++j) rank += (cand[j] > ki) ? 1 : 0;
            if (rank < K) {
                if (isPos) d_posidx[eb * POS_CAP + rank] = (int)cand_p[i];
                else       d_negidx[eb * R + rank] = (int)cand_p[i];
            }
        }
        __syncthreads();
    }

    // ---------- emit ----------
    if (tid == 0) s_miss = 0;
    __syncthreads();
    if (tid < G) {
        if (gt[((size_t)eb * G + tid) * 5 + 4] != 0.0f && d_matched[eb * G + tid] == 0)
            atomicAdd(&s_miss, 1);
    }

    if (tid < R) {
        int s = tid;
        int np = min(d_poscount[eb], POS_CAP);
        int nn = min(R - np, d_negcount[eb]);

        float de0 = 0, de1 = 0, de2 = 0, de3 = 0, de4 = 0;
        float c0 = 0, c1 = 0;
        float r0 = 0, r1 = 0, r2 = 0, r3 = 0, r4 = 0;

        bool is_pos = s < np;
        bool is_real = s < np + nn;

        if (is_real) {
            int idx = is_pos ? d_posidx[eb * POS_CAP + s] : d_negidx[eb * R + (s - np)];
            const float* pp = pr + ((size_t)eb * P + idx) * 5;
            r0 = pp[0]; r1 = pp[1]; r2 = pp[2]; r3 = pp[3]; r4 = 1.0f;
            c1 = 1.0f;
            if (is_pos) {
                int g = d_parg[(size_t)eb * P + idx];
                const float* gp = gt + ((size_t)eb * G + g) * 5;
                float g0 = gp[0], g1 = gp[1], g2 = gp[2], g3 = gp[3];
                float h = r2 - r0, w = r3 - r1;
                float gh = g2 - g0, gw = g3 - g1;
                float cy = (r2 + r0) * 0.5f, cx = (r3 + r1) * 0.5f;
                float gcy = (g2 + g0) * 0.5f, gcx = (g3 + g1) * 0.5f;
                de0 = ((gcy - cy) / h) / 0.1f;
                de1 = ((gcx - cx) / w) / 0.1f;
                de2 = logf(fmaxf(gh / h, 1e-8f)) / 0.2f;
                de3 = logf(fmaxf(gw / w, 1e-8f)) / 0.2f;
                de4 = 1.0f;
                c0 = (float)gcls[((size_t)eb * G + g) * 2 + 0];
            } else {
                de4 = -1.0f;
            }
        }

        size_t sl = (size_t)eb * R + s;
        float* dd = out + sl * 5;
        dd[0] = de0; dd[1] = de1; dd[2] = de2; dd[3] = de3; dd[4] = de4;
        float* cc = out + (size_t)B * R * 5 + sl * 2;
        cc[0] = c0; cc[1] = c1;
        float* rr = out + (size_t)B * R * 5 + (size_t)B * R * 2 + sl * 5;
        rr[0] = r0; rr[1] = r1; rr[2] = r2; rr[3] = r3; rr[4] = r4;
    }

    __syncthreads();
    if (tid == 0) miss_out[eb] = (float)s_miss;
}

// ---------------- launch ----------------
extern "C" void kernel_launch(void* const* d_in, const int* in_sizes, int n_in,
                              void* d_out, int out_size) {
    const float* gt = (const float*)d_in[0];
    const int* gcls = (const int*)d_in[1];
    const float* pr = (const float*)d_in[2];
    float* out = (float*)d_out;

    float* miss_out = out + (size_t)B * R * 5 + (size_t)B * R * 2 + (size_t)B * R * 5;

    k_init<<<8, 256>>>();
    k_main<<<NB, 512>>>(gt, gcls, pr, out, miss_out);
}